// round 7
// baseline (speedup 1.0000x reference)
#include <cuda_runtime.h>
#include <cuda_bf16.h>
#include <math.h>

// Problem constants
#define BB    4
#define CC    256
#define HH    256
#define WW    256
#define HWSZ  (HH * WW)
#define NROI  2048
#define FEAT  2304          // 9 * 256
#define DD    256

// Scratch (device globals; no allocation allowed)
__device__ float g_fmT[(size_t)BB * HWSZ * CC];       // [B,H,W,C]
__device__ float g_xfeat[(size_t)NROI * FEAT];
__device__ float g_part1[(size_t)4 * NROI * DD];      // sh1 split-K partials
__device__ float g_part2[(size_t)2 * NROI * DD];      // sh2 split-K partials
__device__ float g_bufL1[(size_t)3 * NROI * DD];
__device__ float g_bufL2[(size_t)3 * NROI * DD];

// ---------------------------------------------------------------------------
// K0: transpose [B,C,H,W] -> [B,H,W,C]
// ---------------------------------------------------------------------------
__global__ __launch_bounds__(256) void transpose_kernel(const float* __restrict__ fm) {
    __shared__ float tile[32][33];
    int b   = blockIdx.z;
    int hw0 = blockIdx.x * 32;
    int c0  = blockIdx.y * 32;
    int tx = threadIdx.x, ty = threadIdx.y;      // 32 x 8
    const float* src = fm + (size_t)b * CC * HWSZ;
    #pragma unroll
    for (int k = 0; k < 4; k++) {
        int c = c0 + ty + 8 * k;
        tile[ty + 8 * k][tx] = src[(size_t)c * HWSZ + hw0 + tx];
    }
    __syncthreads();
    float* dst = g_fmT + (size_t)b * HWSZ * CC;
    #pragma unroll
    for (int k = 0; k < 4; k++) {
        int hw = hw0 + ty + 8 * k;
        dst[(size_t)hw * CC + c0 + tx] = tile[tx][ty + 8 * k];
    }
}

// ---------------------------------------------------------------------------
// K1: rotated ROI align -> x features [N, 9*256] (f = p*256 + c)
// ---------------------------------------------------------------------------
__global__ __launch_bounds__(256) void roi_kernel(const float* __restrict__ boxes,
                                                  const int* __restrict__ bidx) {
    int n = blockIdx.x;
    int c = threadIdx.x;   // channel

    __shared__ int   s_i00[36], s_i01[36], s_i10[36], s_i11[36];
    __shared__ float s_w[36][4];

    if (c < 36) {
        int s  = c;
        int ix = s & 1;
        int iy = (s >> 1) & 1;
        int p  = s >> 2;
        int pw = p % 3;
        int ph = p / 3;

        float b0 = boxes[n * 7 + 0];
        float b1 = boxes[n * 7 + 1];
        float b4 = boxes[n * 7 + 4];
        float b5 = boxes[n * 7 + 5];
        float b6 = boxes[n * 7 + 6];

        const float gw = 102.4f / 256.0f;
        float cx = (b0 + 51.2f) / gw - 0.5f;
        float cy = (b1 + 51.2f) / gw - 0.5f;
        float rw = b5 / gw;
        float rh = b4 / gw;
        float theta = -b6;
        float ct = cosf(theta), st = sinf(theta);
        float bin_h = rh / 3.0f, bin_w = rw / 3.0f;

        float sgy = ((float)iy + 0.5f) * 0.5f;
        float sgx = ((float)ix + 0.5f) * 0.5f;
        float yy = -rh * 0.5f + ((float)ph + sgy) * bin_h;
        float xx = -rw * 0.5f + ((float)pw + sgx) * bin_w;
        float y = yy * ct - xx * st + cy;
        float x = yy * st + xx * ct + cx;

        bool valid = (y > -1.0f) && (y < (float)HH) && (x > -1.0f) && (x < (float)WW);
        y = fminf(fmaxf(y, 0.0f), (float)(HH - 1));
        x = fminf(fmaxf(x, 0.0f), (float)(WW - 1));
        int y0 = min((int)floorf(y), HH - 1);
        int x0 = min((int)floorf(x), WW - 1);
        int y1 = min(y0 + 1, HH - 1);
        int x1 = min(x0 + 1, WW - 1);
        float ly = y - (float)y0, lx = x - (float)x0;
        float hy = 1.0f - ly, hx = 1.0f - lx;
        float v = valid ? 1.0f : 0.0f;

        s_i00[s] = y0 * WW + x0;
        s_i01[s] = y0 * WW + x1;
        s_i10[s] = y1 * WW + x0;
        s_i11[s] = y1 * WW + x1;
        s_w[s][0] = hy * hx * v;
        s_w[s][1] = hy * lx * v;
        s_w[s][2] = ly * hx * v;
        s_w[s][3] = ly * lx * v;
    }
    __syncthreads();

    int b = bidx[n];
    const float* base = g_fmT + (size_t)b * HWSZ * CC + c;

    float acc[9];
    #pragma unroll
    for (int p = 0; p < 9; p++) acc[p] = 0.0f;

    #pragma unroll
    for (int s = 0; s < 36; s++) {
        float v = s_w[s][0] * base[(size_t)s_i00[s] * CC]
                + s_w[s][1] * base[(size_t)s_i01[s] * CC]
                + s_w[s][2] * base[(size_t)s_i10[s] * CC]
                + s_w[s][3] * base[(size_t)s_i11[s] * CC];
        acc[s >> 2] += v;
    }

    float* o = g_xfeat + (size_t)n * FEAT + c;
    #pragma unroll
    for (int p = 0; p < 9; p++) o[p * CC] = acc[p] * 0.25f;
}

// ---------------------------------------------------------------------------
// K2: 3xTF32 tensor-core GEMM with split-K and fused partial-sum+relu input.
// CTA tile 64x64, 128 threads (4 warps of 32x32), k-step 16.
//
//  splitK=1 : blockIdx.z selects the k-chunk; A/W offset by z*Kchunk in k;
//             C -> partial buffer z (raw, no relu).
//  splitK=0 : blockIdx.z selects branch (W0/W1/W2); A offset aZstride*z.
//  nParts>1 : A element = relu(sum of nParts partial buffers, stride partStride).
// ---------------------------------------------------------------------------
__device__ __forceinline__ unsigned cvt_tf32(float x) {
    unsigned u;
    asm("cvt.rna.tf32.f32 %0, %1;" : "=r"(u) : "f"(x));
    return u;
}

__device__ __forceinline__ void mma8(float* c, const unsigned* a, const unsigned* b) {
    asm volatile(
        "mma.sync.aligned.m16n8k8.row.col.f32.tf32.tf32.f32 "
        "{%0,%1,%2,%3}, {%4,%5,%6,%7}, {%8,%9}, {%0,%1,%2,%3};\n"
        : "+f"(c[0]), "+f"(c[1]), "+f"(c[2]), "+f"(c[3])
        : "r"(a[0]), "r"(a[1]), "r"(a[2]), "r"(a[3]), "r"(b[0]), "r"(b[1]));
}

__device__ __forceinline__ float4 ldA4(const float* p, int nParts, size_t ps) {
    float4 v = *(const float4*)p;
    if (nParts > 1) {
        #pragma unroll 4
        for (int i = 1; i < nParts; i++) {
            float4 q = *(const float4*)(p + (size_t)i * ps);
            v.x += q.x; v.y += q.y; v.z += q.z; v.w += q.w;
        }
        v.x = fmaxf(v.x, 0.0f); v.y = fmaxf(v.y, 0.0f);
        v.z = fmaxf(v.z, 0.0f); v.w = fmaxf(v.w, 0.0f);
    }
    return v;
}

#define SPAD 20

__global__ __launch_bounds__(128) void gemm_tf32x3_kernel(
    const float* __restrict__ A, size_t aZstride, int nParts, size_t partStride,
    int Krow, int Kchunk, int splitK,
    const float* __restrict__ W0, const float* __restrict__ W1,
    const float* __restrict__ W2,
    float* __restrict__ C, size_t cZstride, int reluOut)
{
    __shared__ unsigned AsH[64][SPAD], AsL[64][SPAD];
    __shared__ unsigned BsH[64][SPAD], BsL[64][SPAD];

    int z = blockIdx.z;
    const float* Wm = splitK ? W0 : ((z == 0) ? W0 : (z == 1) ? W1 : W2);
    int kBase = splitK ? z * Kchunk : 0;
    if (!splitK) A += aZstride * (size_t)z;
    C += cZstride * (size_t)z;

    int row0 = blockIdx.y * 64, col0 = blockIdx.x * 64;
    int tid  = threadIdx.x;
    int warp = tid >> 5, lane = tid & 31;
    int g = lane >> 2, tg = lane & 3;
    int wm = (warp >> 1) * 32, wn = (warp & 1) * 32;

    int lr = tid >> 1;           // 0..63 (tile row)
    int lq = (tid & 1) * 8;      // 0 or 8 (k chunk)

    const float* Ag = A  + (size_t)(row0 + lr) * Krow + kBase + lq;
    const float* Wg = Wm + (size_t)(col0 + lr) * Krow + kBase + lq;

    float ra[8], rw[8];
    {
        float4 t0 = ldA4(Ag,     nParts, partStride);
        float4 t1 = ldA4(Ag + 4, nParts, partStride);
        float4 t2 = *(const float4*)(Wg);
        float4 t3 = *(const float4*)(Wg + 4);
        ra[0]=t0.x; ra[1]=t0.y; ra[2]=t0.z; ra[3]=t0.w;
        ra[4]=t1.x; ra[5]=t1.y; ra[6]=t1.z; ra[7]=t1.w;
        rw[0]=t2.x; rw[1]=t2.y; rw[2]=t2.z; rw[3]=t2.w;
        rw[4]=t3.x; rw[5]=t3.y; rw[6]=t3.z; rw[7]=t3.w;
    }

    float acc[2][4][4];
    #pragma unroll
    for (int i = 0; i < 2; i++)
        #pragma unroll
        for (int j = 0; j < 4; j++)
            #pragma unroll
            for (int k = 0; k < 4; k++) acc[i][j][k] = 0.0f;

    for (int k0 = 0; k0 < Kchunk; k0 += 16) {
        __syncthreads();
        #pragma unroll
        for (int i = 0; i < 8; i++) {
            unsigned hA = cvt_tf32(ra[i]);
            AsH[lr][lq + i] = hA;
            AsL[lr][lq + i] = cvt_tf32(ra[i] - __uint_as_float(hA));
            unsigned hW = cvt_tf32(rw[i]);
            BsH[lr][lq + i] = hW;
            BsL[lr][lq + i] = cvt_tf32(rw[i] - __uint_as_float(hW));
        }
        __syncthreads();

        if (k0 + 16 < Kchunk) {
            float4 t0 = ldA4(Ag + k0 + 16, nParts, partStride);
            float4 t1 = ldA4(Ag + k0 + 20, nParts, partStride);
            float4 t2 = *(const float4*)(Wg + k0 + 16);
            float4 t3 = *(const float4*)(Wg + k0 + 20);
            ra[0]=t0.x; ra[1]=t0.y; ra[2]=t0.z; ra[3]=t0.w;
            ra[4]=t1.x; ra[5]=t1.y; ra[6]=t1.z; ra[7]=t1.w;
            rw[0]=t2.x; rw[1]=t2.y; rw[2]=t2.z; rw[3]=t2.w;
            rw[4]=t3.x; rw[5]=t3.y; rw[6]=t3.z; rw[7]=t3.w;
        }

        #pragma unroll
        for (int kk = 0; kk < 16; kk += 8) {
            unsigned aH[2][4], aL[2][4], bH[4][2], bL[4][2];
            #pragma unroll
            for (int mt = 0; mt < 2; mt++) {
                int r = wm + mt * 16 + g;
                aH[mt][0] = AsH[r][kk + tg];
                aH[mt][1] = AsH[r + 8][kk + tg];
                aH[mt][2] = AsH[r][kk + tg + 4];
                aH[mt][3] = AsH[r + 8][kk + tg + 4];
                aL[mt][0] = AsL[r][kk + tg];
                aL[mt][1] = AsL[r + 8][kk + tg];
                aL[mt][2] = AsL[r][kk + tg + 4];
                aL[mt][3] = AsL[r + 8][kk + tg + 4];
            }
            #pragma unroll
            for (int nt = 0; nt < 4; nt++) {
                int nn = wn + nt * 8 + g;
                bH[nt][0] = BsH[nn][kk + tg];
                bH[nt][1] = BsH[nn][kk + tg + 4];
                bL[nt][0] = BsL[nn][kk + tg];
                bL[nt][1] = BsL[nn][kk + tg + 4];
            }
            #pragma unroll
            for (int mt = 0; mt < 2; mt++)
                #pragma unroll
                for (int nt = 0; nt < 4; nt++) {
                    mma8(acc[mt][nt], aH[mt], bH[nt]);
                    mma8(acc[mt][nt], aL[mt], bH[nt]);
                    mma8(acc[mt][nt], aH[mt], bL[nt]);
                }
        }
    }

    #pragma unroll
    for (int mt = 0; mt < 2; mt++) {
        int r = row0 + wm + mt * 16 + g;
        #pragma unroll
        for (int nt = 0; nt < 4; nt++) {
            int cb = col0 + wn + nt * 8 + 2 * tg;
            float2 v0, v1;
            if (reluOut) {
                v0.x = fmaxf(acc[mt][nt][0], 0.0f);
                v0.y = fmaxf(acc[mt][nt][1], 0.0f);
                v1.x = fmaxf(acc[mt][nt][2], 0.0f);
                v1.y = fmaxf(acc[mt][nt][3], 0.0f);
            } else {
                v0.x = acc[mt][nt][0]; v0.y = acc[mt][nt][1];
                v1.x = acc[mt][nt][2]; v1.y = acc[mt][nt][3];
            }
            *(float2*)&C[(size_t)r * DD + cb]       = v0;
            *(float2*)&C[(size_t)(r + 8) * DD + cb] = v1;
        }
    }
}

// ---------------------------------------------------------------------------
// K3: all three heads in one launch. Warp per (branch, row).
// ---------------------------------------------------------------------------
__global__ __launch_bounds__(256) void head_all_kernel(
    const float* __restrict__ Abase,
    const float* __restrict__ w_cls3, const float* __restrict__ b_cls3,
    const float* __restrict__ w_iou3, const float* __restrict__ b_iou3,
    const float* __restrict__ w_reg3, const float* __restrict__ b_reg3,
    float* __restrict__ out, int N)
{
    int gw   = (int)((blockIdx.x * blockDim.x + threadIdx.x) >> 5);
    int lane = threadIdx.x & 31;
    if (gw >= 3 * N) return;
    int br = gw / N, n = gw % N;

    const float* a = Abase + (size_t)br * N * DD + (size_t)n * DD;
    float av[8];
    #pragma unroll
    for (int i = 0; i < 8; i++) av[i] = a[lane + 32 * i];

    const float* Wm = (br == 0) ? w_cls3 : (br == 1) ? w_iou3 : w_reg3;
    const float* bs = (br == 0) ? b_cls3 : (br == 1) ? b_iou3 : b_reg3;
    int Dout = (br == 2) ? 7 : 1;
    float* o = out + ((br == 0) ? n : (br == 1) ? (N + n) : (2 * N + n * 7));

    for (int d = 0; d < Dout; d++) {
        const float* w = Wm + (size_t)d * DD;
        float s = 0.0f;
        #pragma unroll
        for (int i = 0; i < 8; i++) s = fmaf(av[i], w[lane + 32 * i], s);
        #pragma unroll
        for (int off = 16; off > 0; off >>= 1)
            s += __shfl_xor_sync(0xffffffffu, s, off);
        if (lane == 0) o[d] = s + bs[d];
    }
}

// ---------------------------------------------------------------------------
extern "C" void kernel_launch(void* const* d_in, const int* in_sizes, int n_in,
                              void* d_out, int out_size) {
    const float* fm     = (const float*)d_in[0];
    const float* boxes  = (const float*)d_in[1];
    const int*   bidx   = (const int*)  d_in[2];
    const float* w_sh1  = (const float*)d_in[3];
    const float* w_sh2  = (const float*)d_in[4];
    const float* w_cls1 = (const float*)d_in[5];
    const float* w_cls2 = (const float*)d_in[6];
    const float* w_cls3 = (const float*)d_in[7];
    const float* b_cls3 = (const float*)d_in[8];
    const float* w_iou1 = (const float*)d_in[9];
    const float* w_iou2 = (const float*)d_in[10];
    const float* w_iou3 = (const float*)d_in[11];
    const float* b_iou3 = (const float*)d_in[12];
    const float* w_reg1 = (const float*)d_in[13];
    const float* w_reg2 = (const float*)d_in[14];
    const float* w_reg3 = (const float*)d_in[15];
    const float* b_reg3 = (const float*)d_in[16];

    float* out = (float*)d_out;
    int N = in_sizes[2];   // 2048

    float *xfeat, *part1, *part2, *bufL1, *bufL2;
    cudaGetSymbolAddress((void**)&xfeat, g_xfeat);
    cudaGetSymbolAddress((void**)&part1, g_part1);
    cudaGetSymbolAddress((void**)&part2, g_part2);
    cudaGetSymbolAddress((void**)&bufL1, g_bufL1);
    cudaGetSymbolAddress((void**)&bufL2, g_bufL2);

    // 0) transpose feature map to channels-last
    transpose_kernel<<<dim3(HWSZ / 32, CC / 32, BB), dim3(32, 8)>>>(fm);

    // 1) rotated ROI align
    roi_kernel<<<N, 256>>>(boxes, bidx);

    dim3 blk(128);
    size_t sND = (size_t)N * DD;

    // 2) sh1: split-K x4 (K=2304 -> 4*576), raw partials
    gemm_tf32x3_kernel<<<dim3(DD / 64, N / 64, 4), blk>>>(
        xfeat, 0, 1, 0, FEAT, FEAT / 4, 1,
        w_sh1, w_sh1, w_sh1, part1, sND, 0);

    // 3) sh2: fused relu(sum of 4 partials) input, split-K x2 (K=256 -> 2*128)
    gemm_tf32x3_kernel<<<dim3(DD / 64, N / 64, 2), blk>>>(
        part1, 0, 4, sND, DD, DD / 2, 1,
        w_sh2, w_sh2, w_sh2, part2, sND, 0);

    // 4) branch layer 1: fused relu(sum of 2 partials), batched over 3 branches
    gemm_tf32x3_kernel<<<dim3(DD / 64, N / 64, 3), blk>>>(
        part2, 0, 2, sND, DD, DD, 0,
        w_cls1, w_iou1, w_reg1, bufL1, sND, 1);

    // 5) branch layer 2: batched over 3 branches
    gemm_tf32x3_kernel<<<dim3(DD / 64, N / 64, 3), blk>>>(
        bufL1, sND, 1, 0, DD, DD, 0,
        w_cls2, w_iou2, w_reg2, bufL2, sND, 1);

    // 6) all heads in one launch
    int hblocks = (3 * N * 32 + 255) / 256;
    head_all_kernel<<<hblocks, 256>>>(bufL2, w_cls3, b_cls3, w_iou3, b_iou3,
                                      w_reg3, b_reg3, out, N);
}

// round 8
// speedup vs baseline: 1.7906x; 1.7906x over previous
#include <cuda_runtime.h>
#include <cuda_bf16.h>
#include <math.h>

// Problem constants
#define BB    4
#define CC    256
#define HH    256
#define WW    256
#define HWSZ  (HH * WW)
#define NROI  2048
#define FEAT  2304          // 9 * 256
#define DD    256

// Scratch (device globals; no allocation allowed)
__device__ float g_fmT[(size_t)BB * HWSZ * CC];       // [B,H,W,C]
__device__ float g_xfeat[(size_t)NROI * FEAT];
__device__ float g_part1[(size_t)4 * NROI * DD];      // sh1 split-K partials
__device__ float g_bufA[(size_t)NROI * DD];
__device__ float g_bufSH[(size_t)NROI * DD];
__device__ float g_bufL1[(size_t)3 * NROI * DD];
__device__ float g_bufL2[(size_t)3 * NROI * DD];

// ---------------------------------------------------------------------------
// K0: transpose [B,C,H,W] -> [B,H,W,C]
// ---------------------------------------------------------------------------
__global__ __launch_bounds__(256) void transpose_kernel(const float* __restrict__ fm) {
    __shared__ float tile[32][33];
    int b   = blockIdx.z;
    int hw0 = blockIdx.x * 32;
    int c0  = blockIdx.y * 32;
    int tx = threadIdx.x, ty = threadIdx.y;      // 32 x 8
    const float* src = fm + (size_t)b * CC * HWSZ;
    #pragma unroll
    for (int k = 0; k < 4; k++) {
        int c = c0 + ty + 8 * k;
        tile[ty + 8 * k][tx] = src[(size_t)c * HWSZ + hw0 + tx];
    }
    __syncthreads();
    float* dst = g_fmT + (size_t)b * HWSZ * CC;
    #pragma unroll
    for (int k = 0; k < 4; k++) {
        int hw = hw0 + ty + 8 * k;
        dst[(size_t)hw * CC + c0 + tx] = tile[tx][ty + 8 * k];
    }
}

// ---------------------------------------------------------------------------
// K1: rotated ROI align -> x features [N, 9*256] (f = p*256 + c)
// ---------------------------------------------------------------------------
__global__ __launch_bounds__(256) void roi_kernel(const float* __restrict__ boxes,
                                                  const int* __restrict__ bidx) {
    int n = blockIdx.x;
    int c = threadIdx.x;   // channel

    __shared__ int   s_i00[36], s_i01[36], s_i10[36], s_i11[36];
    __shared__ float s_w[36][4];

    if (c < 36) {
        int s  = c;
        int ix = s & 1;
        int iy = (s >> 1) & 1;
        int p  = s >> 2;
        int pw = p % 3;
        int ph = p / 3;

        float b0 = boxes[n * 7 + 0];
        float b1 = boxes[n * 7 + 1];
        float b4 = boxes[n * 7 + 4];
        float b5 = boxes[n * 7 + 5];
        float b6 = boxes[n * 7 + 6];

        const float gw = 102.4f / 256.0f;
        float cx = (b0 + 51.2f) / gw - 0.5f;
        float cy = (b1 + 51.2f) / gw - 0.5f;
        float rw = b5 / gw;
        float rh = b4 / gw;
        float theta = -b6;
        float ct = cosf(theta), st = sinf(theta);
        float bin_h = rh / 3.0f, bin_w = rw / 3.0f;

        float sgy = ((float)iy + 0.5f) * 0.5f;
        float sgx = ((float)ix + 0.5f) * 0.5f;
        float yy = -rh * 0.5f + ((float)ph + sgy) * bin_h;
        float xx = -rw * 0.5f + ((float)pw + sgx) * bin_w;
        float y = yy * ct - xx * st + cy;
        float x = yy * st + xx * ct + cx;

        bool valid = (y > -1.0f) && (y < (float)HH) && (x > -1.0f) && (x < (float)WW);
        y = fminf(fmaxf(y, 0.0f), (float)(HH - 1));
        x = fminf(fmaxf(x, 0.0f), (float)(WW - 1));
        int y0 = min((int)floorf(y), HH - 1);
        int x0 = min((int)floorf(x), WW - 1);
        int y1 = min(y0 + 1, HH - 1);
        int x1 = min(x0 + 1, WW - 1);
        float ly = y - (float)y0, lx = x - (float)x0;
        float hy = 1.0f - ly, hx = 1.0f - lx;
        float v = valid ? 1.0f : 0.0f;

        s_i00[s] = y0 * WW + x0;
        s_i01[s] = y0 * WW + x1;
        s_i10[s] = y1 * WW + x0;
        s_i11[s] = y1 * WW + x1;
        s_w[s][0] = hy * hx * v;
        s_w[s][1] = hy * lx * v;
        s_w[s][2] = ly * hx * v;
        s_w[s][3] = ly * lx * v;
    }
    __syncthreads();

    int b = bidx[n];
    const float* base = g_fmT + (size_t)b * HWSZ * CC + c;

    float acc[9];
    #pragma unroll
    for (int p = 0; p < 9; p++) acc[p] = 0.0f;

    #pragma unroll
    for (int s = 0; s < 36; s++) {
        float v = s_w[s][0] * base[(size_t)s_i00[s] * CC]
                + s_w[s][1] * base[(size_t)s_i01[s] * CC]
                + s_w[s][2] * base[(size_t)s_i10[s] * CC]
                + s_w[s][3] * base[(size_t)s_i11[s] * CC];
        acc[s >> 2] += v;
    }

    float* o = g_xfeat + (size_t)n * FEAT + c;
    #pragma unroll
    for (int p = 0; p < 9; p++) o[p * CC] = acc[p] * 0.25f;
}

// ---------------------------------------------------------------------------
// K2: 3xBF16 tensor-core GEMM.  C[M,DD] = [relu](A[M,K] @ W[DD,K]^T)
// CTA tile 64x64, 128 threads (4 warps of 32x32), k-step 16 (m16n8k16.bf16).
// a = aH + aL (bf16 hi/lo);  D += aH*wH + aL*wH + aH*wL   (~2^-17 accuracy).
//
// smem: [64 rows][12 words]; word = bf16x2 (k-pair). Swizzle: word index
// kw ^ (4*bit3(row)) -> conflict-free frag LDS, STS.128 stores.
//
//  kSplit=1: blockIdx.z picks k-chunk; C -> partial buffer z (raw).
//  kSplit=0: blockIdx.z picks branch weights W0/W1/W2; A offset aZstride*z.
// ---------------------------------------------------------------------------
__device__ __forceinline__ void mma16(float* c, const unsigned* a, const unsigned* b) {
    asm volatile(
        "mma.sync.aligned.m16n8k16.row.col.f32.bf16.bf16.f32 "
        "{%0,%1,%2,%3}, {%4,%5,%6,%7}, {%8,%9}, {%0,%1,%2,%3};\n"
        : "+f"(c[0]), "+f"(c[1]), "+f"(c[2]), "+f"(c[3])
        : "r"(a[0]), "r"(a[1]), "r"(a[2]), "r"(a[3]), "r"(b[0]), "r"(b[1]));
}

__global__ __launch_bounds__(128) void gemm_bf16x3_kernel(
    const float* __restrict__ A, size_t aZstride,
    int Krow, int Kchunk, int kSplit,
    const float* __restrict__ W0, const float* __restrict__ W1,
    const float* __restrict__ W2,
    float* __restrict__ C, size_t cZstride, int reluOut)
{
    __shared__ unsigned AsH[64][12], AsL[64][12];
    __shared__ unsigned BsH[64][12], BsL[64][12];

    int z = blockIdx.z;
    const float* Wm = kSplit ? W0 : ((z == 0) ? W0 : (z == 1) ? W1 : W2);
    int kBase = kSplit ? z * Kchunk : 0;
    if (!kSplit) A += aZstride * (size_t)z;
    C += cZstride * (size_t)z;

    int row0 = blockIdx.y * 64, col0 = blockIdx.x * 64;
    int tid  = threadIdx.x;
    int warp = tid >> 5, lane = tid & 31;
    int g = lane >> 2, tg = lane & 3;
    int wm = (warp >> 1) * 32, wn = (warp & 1) * 32;

    int lr = tid >> 1;                              // 0..63 (smem row)
    int lq = (tid & 1) * 8;                         // k offset 0 or 8
    int sbase = (lq >> 1) ^ (((lr >> 3) & 1) << 2); // swizzled word base (0 or 4)

    const float* Ag = A  + (size_t)(row0 + lr) * Krow + kBase + lq;
    const float* Wg = Wm + (size_t)(col0 + lr) * Krow + kBase + lq;

    float ra[8], rw[8];
    {
        float4 t0 = *(const float4*)(Ag);
        float4 t1 = *(const float4*)(Ag + 4);
        float4 t2 = *(const float4*)(Wg);
        float4 t3 = *(const float4*)(Wg + 4);
        ra[0]=t0.x; ra[1]=t0.y; ra[2]=t0.z; ra[3]=t0.w;
        ra[4]=t1.x; ra[5]=t1.y; ra[6]=t1.z; ra[7]=t1.w;
        rw[0]=t2.x; rw[1]=t2.y; rw[2]=t2.z; rw[3]=t2.w;
        rw[4]=t3.x; rw[5]=t3.y; rw[6]=t3.z; rw[7]=t3.w;
    }

    float acc[2][4][4];
    #pragma unroll
    for (int i = 0; i < 2; i++)
        #pragma unroll
        for (int j = 0; j < 4; j++)
            #pragma unroll
            for (int k = 0; k < 4; k++) acc[i][j][k] = 0.0f;

    for (int k0 = 0; k0 < Kchunk; k0 += 16) {
        __syncthreads();
        {
            unsigned ah[4], al[4], wh[4], wl[4];
            #pragma unroll
            for (int i = 0; i < 4; i++) {
                float x = ra[2 * i], y = ra[2 * i + 1];
                __nv_bfloat162 h = __floats2bfloat162_rn(x, y);
                __nv_bfloat162 l = __floats2bfloat162_rn(x - __low2float(h),
                                                         y - __high2float(h));
                ah[i] = *(unsigned*)&h;
                al[i] = *(unsigned*)&l;
                float u = rw[2 * i], v = rw[2 * i + 1];
                __nv_bfloat162 h2 = __floats2bfloat162_rn(u, v);
                __nv_bfloat162 l2 = __floats2bfloat162_rn(u - __low2float(h2),
                                                          v - __high2float(h2));
                wh[i] = *(unsigned*)&h2;
                wl[i] = *(unsigned*)&l2;
            }
            *(uint4*)&AsH[lr][sbase] = make_uint4(ah[0], ah[1], ah[2], ah[3]);
            *(uint4*)&AsL[lr][sbase] = make_uint4(al[0], al[1], al[2], al[3]);
            *(uint4*)&BsH[lr][sbase] = make_uint4(wh[0], wh[1], wh[2], wh[3]);
            *(uint4*)&BsL[lr][sbase] = make_uint4(wl[0], wl[1], wl[2], wl[3]);
        }
        __syncthreads();

        if (k0 + 16 < Kchunk) {
            float4 t0 = *(const float4*)(Ag + k0 + 16);
            float4 t1 = *(const float4*)(Ag + k0 + 20);
            float4 t2 = *(const float4*)(Wg + k0 + 16);
            float4 t3 = *(const float4*)(Wg + k0 + 20);
            ra[0]=t0.x; ra[1]=t0.y; ra[2]=t0.z; ra[3]=t0.w;
            ra[4]=t1.x; ra[5]=t1.y; ra[6]=t1.z; ra[7]=t1.w;
            rw[0]=t2.x; rw[1]=t2.y; rw[2]=t2.z; rw[3]=t2.w;
            rw[4]=t3.x; rw[5]=t3.y; rw[6]=t3.z; rw[7]=t3.w;
        }

        unsigned aH[2][4], aL[2][4], bHf[4][2], bLf[4][2];
        #pragma unroll
        for (int mt = 0; mt < 2; mt++) {
            int r = wm + mt * 16 + g;        // bit3(r) = 0
            aH[mt][0] = AsH[r][tg];          // a0: row r,   kw=tg
            aH[mt][1] = AsH[r + 8][tg + 4];  // a1: row r+8, kw=tg   (swizzled)
            aH[mt][2] = AsH[r][tg + 4];      // a2: row r,   kw=tg+4
            aH[mt][3] = AsH[r + 8][tg];      // a3: row r+8, kw=tg+4 (swizzled)
            aL[mt][0] = AsL[r][tg];
            aL[mt][1] = AsL[r + 8][tg + 4];
            aL[mt][2] = AsL[r][tg + 4];
            aL[mt][3] = AsL[r + 8][tg];
        }
        #pragma unroll
        for (int nt = 0; nt < 4; nt++) {
            int n = wn + nt * 8 + g;
            int s = (nt & 1) << 2;           // bit3(n) = nt&1
            bHf[nt][0] = BsH[n][tg ^ s];
            bHf[nt][1] = BsH[n][(tg + 4) ^ s];
            bLf[nt][0] = BsL[n][tg ^ s];
            bLf[nt][1] = BsL[n][(tg + 4) ^ s];
        }
        #pragma unroll
        for (int mt = 0; mt < 2; mt++)
            #pragma unroll
            for (int nt = 0; nt < 4; nt++) {
                mma16(acc[mt][nt], aH[mt], bHf[nt]);
                mma16(acc[mt][nt], aL[mt], bHf[nt]);
                mma16(acc[mt][nt], aH[mt], bLf[nt]);
            }
    }

    #pragma unroll
    for (int mt = 0; mt < 2; mt++) {
        int r = row0 + wm + mt * 16 + g;
        #pragma unroll
        for (int nt = 0; nt < 4; nt++) {
            int cb = col0 + wn + nt * 8 + 2 * tg;
            float2 v0, v1;
            if (reluOut) {
                v0.x = fmaxf(acc[mt][nt][0], 0.0f);
                v0.y = fmaxf(acc[mt][nt][1], 0.0f);
                v1.x = fmaxf(acc[mt][nt][2], 0.0f);
                v1.y = fmaxf(acc[mt][nt][3], 0.0f);
            } else {
                v0.x = acc[mt][nt][0]; v0.y = acc[mt][nt][1];
                v1.x = acc[mt][nt][2]; v1.y = acc[mt][nt][3];
            }
            *(float2*)&C[(size_t)r * DD + cb]       = v0;
            *(float2*)&C[(size_t)(r + 8) * DD + cb] = v1;
        }
    }
}

// ---------------------------------------------------------------------------
// K2b: reduce 4 split-K partials + relu (vectorized)
// ---------------------------------------------------------------------------
__global__ __launch_bounds__(256) void reduce4_relu_kernel(
    const float* __restrict__ p, float* __restrict__ out, int n4)
{
    int i = blockIdx.x * blockDim.x + threadIdx.x;
    if (i >= n4) return;
    const float4* p4 = (const float4*)p;
    float4 a = p4[i];
    float4 b = p4[i + n4];
    float4 c = p4[i + 2 * n4];
    float4 d = p4[i + 3 * n4];
    float4 o;
    o.x = fmaxf(a.x + b.x + c.x + d.x, 0.0f);
    o.y = fmaxf(a.y + b.y + c.y + d.y, 0.0f);
    o.z = fmaxf(a.z + b.z + c.z + d.z, 0.0f);
    o.w = fmaxf(a.w + b.w + c.w + d.w, 0.0f);
    ((float4*)out)[i] = o;
}

// ---------------------------------------------------------------------------
// K3: all three heads in one launch. Warp per (branch, row).
// ---------------------------------------------------------------------------
__global__ __launch_bounds__(256) void head_all_kernel(
    const float* __restrict__ Abase,
    const float* __restrict__ w_cls3, const float* __restrict__ b_cls3,
    const float* __restrict__ w_iou3, const float* __restrict__ b_iou3,
    const float* __restrict__ w_reg3, const float* __restrict__ b_reg3,
    float* __restrict__ out, int N)
{
    int gw   = (int)((blockIdx.x * blockDim.x + threadIdx.x) >> 5);
    int lane = threadIdx.x & 31;
    if (gw >= 3 * N) return;
    int br = gw / N, n = gw % N;

    const float* a = Abase + (size_t)br * N * DD + (size_t)n * DD;
    float av[8];
    #pragma unroll
    for (int i = 0; i < 8; i++) av[i] = a[lane + 32 * i];

    const float* Wm = (br == 0) ? w_cls3 : (br == 1) ? w_iou3 : w_reg3;
    const float* bs = (br == 0) ? b_cls3 : (br == 1) ? b_iou3 : b_reg3;
    int Dout = (br == 2) ? 7 : 1;
    float* o = out + ((br == 0) ? n : (br == 1) ? (N + n) : (2 * N + n * 7));

    for (int d = 0; d < Dout; d++) {
        const float* w = Wm + (size_t)d * DD;
        float s = 0.0f;
        #pragma unroll
        for (int i = 0; i < 8; i++) s = fmaf(av[i], w[lane + 32 * i], s);
        #pragma unroll
        for (int off = 16; off > 0; off >>= 1)
            s += __shfl_xor_sync(0xffffffffu, s, off);
        if (lane == 0) o[d] = s + bs[d];
    }
}

// ---------------------------------------------------------------------------
extern "C" void kernel_launch(void* const* d_in, const int* in_sizes, int n_in,
                              void* d_out, int out_size) {
    const float* fm     = (const float*)d_in[0];
    const float* boxes  = (const float*)d_in[1];
    const int*   bidx   = (const int*)  d_in[2];
    const float* w_sh1  = (const float*)d_in[3];
    const float* w_sh2  = (const float*)d_in[4];
    const float* w_cls1 = (const float*)d_in[5];
    const float* w_cls2 = (const float*)d_in[6];
    const float* w_cls3 = (const float*)d_in[7];
    const float* b_cls3 = (const float*)d_in[8];
    const float* w_iou1 = (const float*)d_in[9];
    const float* w_iou2 = (const float*)d_in[10];
    const float* w_iou3 = (const float*)d_in[11];
    const float* b_iou3 = (const float*)d_in[12];
    const float* w_reg1 = (const float*)d_in[13];
    const float* w_reg2 = (const float*)d_in[14];
    const float* w_reg3 = (const float*)d_in[15];
    const float* b_reg3 = (const float*)d_in[16];

    float* out = (float*)d_out;
    int N = in_sizes[2];   // 2048

    float *xfeat, *part1, *bufA, *bufSH, *bufL1, *bufL2;
    cudaGetSymbolAddress((void**)&xfeat, g_xfeat);
    cudaGetSymbolAddress((void**)&part1, g_part1);
    cudaGetSymbolAddress((void**)&bufA,  g_bufA);
    cudaGetSymbolAddress((void**)&bufSH, g_bufSH);
    cudaGetSymbolAddress((void**)&bufL1, g_bufL1);
    cudaGetSymbolAddress((void**)&bufL2, g_bufL2);

    // 0) transpose feature map to channels-last
    transpose_kernel<<<dim3(HWSZ / 32, CC / 32, BB), dim3(32, 8)>>>(fm);

    // 1) rotated ROI align
    roi_kernel<<<N, 256>>>(boxes, bidx);

    dim3 blk(128);
    size_t sND = (size_t)N * DD;
    int n4 = (int)(sND / 4);

    // 2) sh1: split-K x4 (K=2304 -> 4*576), raw partials, 512 CTAs
    gemm_bf16x3_kernel<<<dim3(DD / 64, N / 64, 4), blk>>>(
        xfeat, 0, FEAT, FEAT / 4, 1,
        w_sh1, w_sh1, w_sh1, part1, sND, 0);

    // 2b) reduce partials + relu -> bufA
    reduce4_relu_kernel<<<(n4 + 255) / 256, 256>>>(part1, bufA, n4);

    // 3) sh2
    gemm_bf16x3_kernel<<<dim3(DD / 64, N / 64, 1), blk>>>(
        bufA, 0, DD, DD, 0,
        w_sh2, w_sh2, w_sh2, bufSH, 0, 1);

    // 4) branch layer 1 (batched over 3 branches)
    gemm_bf16x3_kernel<<<dim3(DD / 64, N / 64, 3), blk>>>(
        bufSH, 0, DD, DD, 0,
        w_cls1, w_iou1, w_reg1, bufL1, sND, 1);

    // 5) branch layer 2 (batched over 3 branches)
    gemm_bf16x3_kernel<<<dim3(DD / 64, N / 64, 3), blk>>>(
        bufL1, sND, DD, DD, 0,
        w_cls2, w_iou2, w_reg2, bufL2, sND, 1);

    // 6) all heads in one launch
    int hblocks = (3 * N * 32 + 255) / 256;
    head_all_kernel<<<hblocks, 256>>>(bufL2, w_cls3, b_cls3, w_iou3, b_iou3,
                                      w_reg3, b_reg3, out, N);
}